// round 17
// baseline (speedup 1.0000x reference)
#include <cuda_runtime.h>
#include <cuda_fp16.h>
#include <cstdint>

#define Bb 512
#define Ss 128
#define Kk 4
#define Hh 128
#define KH 512
#define EPSQ 1e-9f

typedef unsigned long long u64;

// ---------------- scratch (device globals; no allocation allowed) ----------
__device__ __half g_hat_h[(size_t)Bb * Kk * Ss * Hh];  // 67 MB fp16 hat
__device__ __half g_wh[(size_t)Ss * KH * Hh];          // 16.7 MB w fp16
__device__ __half g_ih[(size_t)Bb * Ss * Hh];          // 16.7 MB item fp16
__device__ float  g_cw  [(size_t)Bb * Kk * Ss];        // capsule_weight
__device__ float  g_dacc[2][Kk * Ss];                  // softmax denominators

// ---------------- mma / async helpers (generic PTX, compute_103-safe) -------
__device__ __forceinline__ void ldsm4(uint32_t* r, uint32_t addr) {
    asm volatile("ldmatrix.sync.aligned.m8n8.x4.shared.b16 {%0,%1,%2,%3}, [%4];"
                 : "=r"(r[0]), "=r"(r[1]), "=r"(r[2]), "=r"(r[3]) : "r"(addr));
}
__device__ __forceinline__ void mma16816(float* d, const uint32_t* a,
                                         uint32_t b0, uint32_t b1) {
    asm volatile(
        "mma.sync.aligned.m16n8k16.row.col.f32.f16.f16.f32 "
        "{%0,%1,%2,%3}, {%4,%5,%6,%7}, {%8,%9}, {%0,%1,%2,%3};"
        : "+f"(d[0]), "+f"(d[1]), "+f"(d[2]), "+f"(d[3])
        : "r"(a[0]), "r"(a[1]), "r"(a[2]), "r"(a[3]), "r"(b0), "r"(b1));
}
__device__ __forceinline__ void cpa16(uint32_t dst, const void* src) {
    asm volatile("cp.async.cg.shared.global [%0], [%1], 16;"
                 :: "r"(dst), "l"(src) : "memory");
}
__device__ __forceinline__ void cpa_wait_all() {
    asm volatile("cp.async.commit_group;\n\tcp.async.wait_group 0;" ::: "memory");
}

// ---------------- pre-convert: fp32 -> fp16 (w and item) --------------------
// grid (8192, 2) x 256: y=0 -> w, y=1 -> item (8.39M floats each)
__global__ void __launch_bounds__(256) presplit(const float* __restrict__ w,
                                                const float* __restrict__ item) {
    const size_t i4 = (size_t)blockIdx.x * 256 + threadIdx.x;   // float4 index
    const float4* src = (blockIdx.y == 0) ? (const float4*)w : (const float4*)item;
    __half* dh = (blockIdx.y == 0) ? g_wh : g_ih;

    float4 v = src[i4];
    __half2 h0 = __floats2half2_rn(v.x, v.y);
    __half2 h1 = __floats2half2_rn(v.z, v.w);
    uint2 hu;
    hu.x = *(uint32_t*)&h0; hu.y = *(uint32_t*)&h1;
    *(uint2*)(dh + i4 * 4) = hu;

    if (blockIdx.x == 0 && blockIdx.y == 0) {
        #pragma unroll
        for (int j = 0; j < 4; j++)
            ((float*)g_dacc)[threadIdx.x + 256 * j] = 0.0f;
    }
}

// ---------------- fp16 tensor-core GEMM (single K=128 stage) -----------------
// hat[b,kcap,s,h] = sum_k item[b,s,k] * w[s, kcap*H+h, k]
// A = w rows (M=128), B = item rows (N=128). Tiles [128 x 128] fp16 = 32KB each.
#define GEMM_SMEM 65536

__global__ void __launch_bounds__(256, 2) gemm_mma() {
    extern __shared__ char smc[];
    const uint32_t sb = (uint32_t)__cvta_generic_to_shared(smc);

    const int tid  = threadIdx.x;
    const int warp = tid >> 5, lane = tid & 31;
    const int kcap = blockIdx.x;
    const int d0   = kcap * 128;
    const int b0   = blockIdx.y * 128;
    const int s    = blockIdx.z;

    const int wm = warp & 1;             // m half (64 rows = 4 m16 tiles)
    const int wn = warp >> 1;            // n quarter (32 = 4 n8 tiles)
    const int m_base = wm * 64;
    const int n_base = wn * 32;

    const __half* Agh = g_wh + ((size_t)s * KH + d0) * Hh;
    const __half* Bgh = g_ih + ((size_t)b0 * Ss + s) * Hh;

    // ldmatrix lane geometry (row pitch = 256B)
    const int q = lane >> 3, rr = lane & 7;
    const int qa = q >> 1;                       // A k-unit low bit
    uint32_t baseA[4]; int m7A[4];
    #pragma unroll
    for (int mt = 0; mt < 4; mt++) {
        const int m = m_base + mt * 16 + ((q & 1) << 3) + rr;
        baseA[mt] = sb + (uint32_t)(m * 256);
        m7A[mt]   = m & 7;
    }
    const int qb = q & 1;                        // B k-unit low bit
    uint32_t baseB[2]; int n7B[2];
    #pragma unroll
    for (int nt2 = 0; nt2 < 2; nt2++) {
        const int n = n_base + nt2 * 16 + ((q >> 1) << 3) + rr;
        baseB[nt2] = sb + 32768u + (uint32_t)(n * 256);
        n7B[nt2]   = n & 7;
    }

    float acc[4][4][4];
    #pragma unroll
    for (int i = 0; i < 4; i++)
        #pragma unroll
        for (int j = 0; j < 4; j++)
            #pragma unroll
            for (int e = 0; e < 4; e++) acc[i][j][e] = 0.0f;

    // ---- stage full K=128: pure cp.async (u = 16B unit 0..15, r0 = 0..15)
    const int u  = tid & 15;
    const int r0 = tid >> 4;
    #pragma unroll
    for (int p = 0; p < 8; p++) {
        const int row = r0 + p * 16;
        const uint32_t so = (uint32_t)(row * 256) + ((uint32_t)(u ^ (row & 7)) << 4);
        cpa16(sb + so,          Agh + (size_t)row * Hh + u * 8);
        cpa16(sb + 32768u + so, Bgh + (size_t)row * (Ss * Hh) + u * 8);
    }
    cpa_wait_all();
    __syncthreads();

    // ---- compute: 8 k16 steps, plain fp16 mma
    #pragma unroll
    for (int kt = 0; kt < 8; kt++) {
        uint32_t bh[8];
        #pragma unroll
        for (int nt2 = 0; nt2 < 2; nt2++) {
            const uint32_t ub = (uint32_t)((2 * kt + qb) ^ n7B[nt2]) << 4;
            ldsm4(&bh[nt2 * 4], baseB[nt2] + ub);
        }
        #pragma unroll
        for (int mt = 0; mt < 4; mt++) {
            uint32_t ah[4];
            const uint32_t ua = (uint32_t)((2 * kt + qa) ^ m7A[mt]) << 4;
            ldsm4(ah, baseA[mt] + ua);
            #pragma unroll
            for (int nt = 0; nt < 4; nt++)
                mma16816(acc[mt][nt], ah, bh[nt * 2], bh[nt * 2 + 1]);
        }
    }
    __syncthreads();

    // ---- epilogue: transpose to [n][m] fp16 (pitch 136), coalesced STG
    __half* smh = (__half*)smc;
    #pragma unroll
    for (int mt = 0; mt < 4; mt++) {
        #pragma unroll
        for (int nt = 0; nt < 4; nt++) {
            const int m = m_base + mt * 16 + (lane >> 2);
            const int n = n_base + nt * 8 + 2 * (lane & 3);
            smh[n * 136 + m]           = __float2half(acc[mt][nt][0]);
            smh[(n + 1) * 136 + m]     = __float2half(acc[mt][nt][1]);
            smh[n * 136 + m + 8]       = __float2half(acc[mt][nt][2]);
            smh[(n + 1) * 136 + m + 8] = __float2half(acc[mt][nt][3]);
        }
    }
    __syncthreads();
    #pragma unroll
    for (int i = tid; i < 2048; i += 256) {
        const int n = i >> 4, uo = i & 15;
        uint4 v = *(const uint4*)&smh[n * 136 + uo * 8];
        const int b = b0 + n;
        *(uint4*)&g_hat_h[(((size_t)b * Kk + kcap) * Ss + s) * Hh + uo * 8] = v;
    }
}

// ---------------- routing iters 0/1: all-register hat, no smem tile ---------
__global__ void __launch_bounds__(256, 4) routing01(const float* __restrict__ mask,
                                                    int iter) {
    __shared__ float sw[Ss];
    __shared__ float cap[Hh];
    __shared__ float red[2048];

    const int bx  = blockIdx.x;   // b*K + k
    const int b   = bx >> 2;
    const int k   = bx & 3;
    const int tid = threadIdx.x;
    const int c4  = tid & 15;     // fixed 8-half column group
    const int rg  = tid >> 4;     // base row 0..15

    // ---- hat sub-block to registers (MLP = 8; v[i] = row rg+16i, cols 8c4..)
    const uint4* src = (const uint4*)(g_hat_h + (size_t)bx * (Ss * Hh));
    uint4 v[8];
    #pragma unroll
    for (int i = 0; i < 8; i++) v[i] = src[tid + i * 256];

    // ---- sw[s]
    if (tid < Ss) {
        float m = mask[b * Ss + tid];
        float x;
        if (iter == 0) {
            x = 1.0f / (float)Bb;                       // softmax over b of zeros
        } else {
            float e = __expf(g_cw[(size_t)bx * Ss + tid]);
            x = e / g_dacc[0][k * Ss + tid];
        }
        sw[tid] = (m == 0.0f) ? 0.0f : x;
    }
    __syncthreads();

    // ---- cap partials from registers
    {
        float2 a0 = make_float2(0.f, 0.f), a1 = a0, a2 = a0, a3 = a0;
        #pragma unroll
        for (int i = 0; i < 8; i++) {
            const float wv = sw[rg + 16 * i];
            float2 f;
            f = __half22float2(*(__half2*)&v[i].x); a0.x += wv * f.x; a0.y += wv * f.y;
            f = __half22float2(*(__half2*)&v[i].y); a1.x += wv * f.x; a1.y += wv * f.y;
            f = __half22float2(*(__half2*)&v[i].z); a2.x += wv * f.x; a2.y += wv * f.y;
            f = __half22float2(*(__half2*)&v[i].w); a3.x += wv * f.x; a3.y += wv * f.y;
        }
        *(float4*)&red[rg * 128 + c4 * 8]     = make_float4(a0.x, a0.y, a1.x, a1.y);
        *(float4*)&red[rg * 128 + c4 * 8 + 4] = make_float4(a2.x, a2.y, a3.x, a3.y);
    }
    __syncthreads();
    if (tid < Hh) {
        float c = 0.0f;
        #pragma unroll
        for (int g = 0; g < 16; g++) c += red[g * 128 + tid];
        cap[tid] = c;
    }
    __syncthreads();

    // ---- squash
    {
        float x = (tid < Hh) ? cap[tid] * cap[tid] : 0.0f;
        #pragma unroll
        for (int off = 16; off; off >>= 1)
            x += __shfl_down_sync(0xffffffffu, x, off);
        if (tid < Hh && (tid & 31) == 0) red[tid >> 5] = x;
        __syncthreads();
        if (tid == 0) {
            float n = red[0] + red[1] + red[2] + red[3];
            red[8] = n / (1.0f + n) * rsqrtf(n + EPSQ);
        }
        __syncthreads();
        float f = red[8];
        if (tid < Hh) cap[tid] *= f;
    }
    __syncthreads();

    // ---- delta from registers: partial dot over this thread's 8 columns,
    //      then 4 xor-shfls across the 16 lanes sharing rg.
    {
        float4 c0 = *(const float4*)&cap[c4 * 8];
        float4 c1 = *(const float4*)&cap[c4 * 8 + 4];
        float d[8];
        #pragma unroll
        for (int i = 0; i < 8; i++) {
            float2 f;
            float t;
            f = __half22float2(*(__half2*)&v[i].x); t  = f.x * c0.x + f.y * c0.y;
            f = __half22float2(*(__half2*)&v[i].y); t += f.x * c0.z + f.y * c0.w;
            f = __half22float2(*(__half2*)&v[i].z); t += f.x * c1.x + f.y * c1.y;
            f = __half22float2(*(__half2*)&v[i].w); t += f.x * c1.z + f.y * c1.w;
            d[i] = t;
        }
        #pragma unroll
        for (int off = 8; off; off >>= 1) {
            #pragma unroll
            for (int i = 0; i < 8; i++)
                d[i] += __shfl_xor_sync(0xffffffffu, d[i], off);
        }
        if (c4 == 0) {
            #pragma unroll
            for (int i = 0; i < 8; i++) {
                const int s = rg + 16 * i;
                size_t idx = (size_t)bx * Ss + s;
                float nc = (iter == 0) ? d[i] : (g_cw[idx] + d[i]);
                g_cw[idx] = nc;
                atomicAdd(&g_dacc[iter][k * Ss + s], __expf(nc));
            }
        }
    }
}

// ---------------- final iteration: fused gmem cap, squash, out --------------
__global__ void __launch_bounds__(256) routing_final(const float* __restrict__ mask,
                                                     float* __restrict__ out) {
    __shared__ float sw[Ss];
    __shared__ float cap[Hh];
    __shared__ float red[2048];

    const int bx  = blockIdx.x;   // b*K + k
    const int b   = bx >> 2;
    const int k   = bx & 3;
    const int tid = threadIdx.x;
    const int c4  = tid & 15;
    const int rg  = tid >> 4;

    // ---- issue hat loads early
    const uint4* src = (const uint4*)(g_hat_h + (size_t)bx * (Ss * Hh));
    uint4 v[8];
    #pragma unroll
    for (int i = 0; i < 8; i++) v[i] = src[tid + i * 256];

    if (tid < Ss) {
        float m = mask[b * Ss + tid];
        float e = __expf(g_cw[(size_t)bx * Ss + tid]);
        float x = e / g_dacc[1][k * Ss + tid];
        sw[tid] = (m == 0.0f) ? 0.0f : x;
    }
    __syncthreads();

    // ---- cap partials from registers
    {
        float2 a0 = make_float2(0.f, 0.f), a1 = a0, a2 = a0, a3 = a0;
        #pragma unroll
        for (int i = 0; i < 8; i++) {
            const float wv = sw[rg + 16 * i];
            float2 f;
            f = __half22float2(*(__half2*)&v[i].x); a0.x += wv * f.x; a0.y += wv * f.y;
            f = __half22float2(*(__half2*)&v[i].y); a1.x += wv * f.x; a1.y += wv * f.y;
            f = __half22float2(*(__half2*)&v[i].z); a2.x += wv * f.x; a2.y += wv * f.y;
            f = __half22float2(*(__half2*)&v[i].w); a3.x += wv * f.x; a3.y += wv * f.y;
        }
        *(float4*)&red[rg * 128 + c4 * 8]     = make_float4(a0.x, a0.y, a1.x, a1.y);
        *(float4*)&red[rg * 128 + c4 * 8 + 4] = make_float4(a2.x, a2.y, a3.x, a3.y);
    }
    __syncthreads();
    if (tid < Hh) {
        float c = 0.0f;
        #pragma unroll
        for (int g = 0; g < 16; g++) c += red[g * 128 + tid];
        cap[tid] = c;
    }
    __syncthreads();

    // squash + output
    {
        float x = (tid < Hh) ? cap[tid] * cap[tid] : 0.0f;
        #pragma unroll
        for (int off = 16; off; off >>= 1)
            x += __shfl_down_sync(0xffffffffu, x, off);
        if (tid < Hh && (tid & 31) == 0) red[tid >> 5] = x;
        __syncthreads();
        if (tid == 0) {
            float n = red[0] + red[1] + red[2] + red[3];
            red[8] = n / (1.0f + n) * rsqrtf(n + EPSQ);
        }
        __syncthreads();
        if (tid < Hh) out[(size_t)bx * Hh + tid] = cap[tid] * red[8];
    }
}

// ---------------- launch -----------------------------------------------------
extern "C" void kernel_launch(void* const* d_in, const int* in_sizes, int n_in,
                              void* d_out, int out_size) {
    const float* item = (const float*)d_in[0];   // [B,S,H]
    const float* mask = (const float*)d_in[1];   // [B,S]
    const float* w    = (const float*)d_in[2];   // [1,S,K*H,H]
    float* out = (float*)d_out;                  // [B,K,H]

    cudaFuncSetAttribute(gemm_mma,
                         cudaFuncAttributeMaxDynamicSharedMemorySize, GEMM_SMEM);

    presplit<<<dim3(8192, 2), 256>>>(w, item);   // also zeroes g_dacc

    dim3 gg(Kk, Bb / 128, Ss);                   // (capsule, b-block, s)
    gemm_mma<<<gg, 256, GEMM_SMEM>>>();

    routing01<<<Bb * Kk, 256>>>(mask, 0);
    routing01<<<Bb * Kk, 256>>>(mask, 1);
    routing_final<<<Bb * Kk, 256>>>(mask, out);
}